// round 12
// baseline (speedup 1.0000x reference)
#include <cuda_runtime.h>
#include <cstdint>

// Problem constants (fixed by the reference)
static constexpr int B  = 2048;   // batch
static constexpr int U  = 256;    // units
static constexpr int P  = 256;    // features
static constexpr int G  = 64;     // groups
static constexpr int UT = 8;      // units per CTA (1 per consumer warp)
static constexpr int SPLIT = 2;   // intra-group batch split (gridDim.z)

static constexpr int HALF_BYTES  = UT * P * 4;        // 8 KB: one batch tile
static constexpr int STAGE_BYTES = 2 * HALF_BYTES;    // 16 KB: two batches
static constexpr int STAGES      = 3;                 // ring stages
static constexpr int CWARPS      = 8;                 // consumer warps
static constexpr int THREADS     = 288;               // 8 consumers + 1 producer
static constexpr int RING_BYTES  = STAGES * STAGE_BYTES;       // 48 KB
static constexpr int SMEM_TOTAL  = RING_BYTES + STAGES * 16;   // + mbarrier pairs

#define SOFTPLUS_C 0.5413248546129181f

// Scratch (allocation-free rule: __device__ globals)
__device__ int g_items[B];        // batch indices sorted by group
__device__ int g_start[G + 1];    // group offsets into g_items

__device__ __forceinline__ float softplus_f(float v) {
    return fmaxf(v, 0.0f) + log1pf(expf(-fabsf(v)));
}

__device__ __forceinline__ float warp_sum(float v) {
    #pragma unroll
    for (int o = 16; o; o >>= 1) v += __shfl_xor_sync(0xffffffffu, v, o);
    return v;
}

// ---- mbarrier helpers (same convention as the R11 kernel, which verified) ----
__device__ __forceinline__ void mbar_init(uint32_t mbar, uint32_t count) {
    asm volatile("mbarrier.init.shared.b64 [%0], %1;" :: "r"(mbar), "r"(count) : "memory");
}
__device__ __forceinline__ void mbar_arrive(uint32_t mbar) {
    asm volatile("mbarrier.arrive.shared.b64 _, [%0];" :: "r"(mbar) : "memory");
}
__device__ __forceinline__ void mbar_expect_tx(uint32_t mbar, uint32_t bytes) {
    asm volatile("mbarrier.arrive.expect_tx.shared.b64 _, [%0], %1;"
                 :: "r"(mbar), "r"(bytes) : "memory");
}
__device__ __forceinline__ void mbar_wait(uint32_t mbar, uint32_t parity) {
    uint32_t done;
    asm volatile(
        "{\n\t.reg .pred p;\n\t"
        "mbarrier.try_wait.parity.acquire.cta.shared::cta.b64 p, [%1], %2;\n\t"
        "selp.b32 %0, 1, 0, p;\n\t}"
        : "=r"(done) : "r"(mbar), "r"(parity) : "memory");
    if (!done) {
        asm volatile(
            "{\n\t.reg .pred P1;\n\t"
            "WAIT_LOOP_%=:\n\t"
            "mbarrier.try_wait.parity.acquire.cta.shared::cta.b64 P1, [%0], %1, 0x989680;\n\t"
            "@P1 bra.uni WAIT_DONE_%=;\n\t"
            "bra.uni WAIT_LOOP_%=;\n\t"
            "WAIT_DONE_%=:\n\t}"
            :: "r"(mbar), "r"(parity) : "memory");
    }
}
// bulk async copy gmem->smem, completion via mbarrier complete_tx (SASS: UBLKCP.S.G)
__device__ __forceinline__ void bulk_copy_g2s(uint32_t dst_smem, const void* src,
                                              uint32_t bytes, uint32_t mbar) {
    asm volatile(
        "cp.async.bulk.shared::cta.global.mbarrier::complete_tx::bytes [%0], [%1], %2, [%3];"
        :: "r"(dst_smem), "l"(src), "r"(bytes), "r"(mbar) : "memory");
}

// ---------------------------------------------------------------------------
// Kernel 1: counting-sort batches by group (single block, tiny)
// ---------------------------------------------------------------------------
__global__ void bin_kernel(const int* __restrict__ gid) {
    __shared__ int cnt[G];
    __shared__ int off[G];
    int tid = threadIdx.x;
    if (tid < G) cnt[tid] = 0;
    __syncthreads();
    for (int b = tid; b < B; b += blockDim.x)
        atomicAdd(&cnt[gid[b]], 1);
    __syncthreads();
    if (tid == 0) {
        int s = 0;
        for (int g = 0; g < G; g++) {
            g_start[g] = s;
            off[g] = s;
            s += cnt[g];
        }
        g_start[G] = s;
    }
    __syncthreads();
    for (int b = tid; b < B; b += blockDim.x) {
        int g = gid[b];
        int pos = atomicAdd(&off[g], 1);
        g_items[pos] = b;   // intra-group order nondeterministic; outputs are
                            // per-batch independent -> results deterministic
    }
}

// ---------------------------------------------------------------------------
// Kernel 2: warp-specialized producer/consumer, 2 BATCHES PER STAGE.
// grid = (U/UT, G, SPLIT), 288 threads. Warps 0-7 consume (1 unit each,
// weights in registers); warp 8 lane 0 produces: per stage, ONE empty-wait +
// ONE expect_tx(16KB) + TWO cp.async.bulk copies (two batch tiles).
// Consumers process one batch per iteration but wait-full only on even
// iterations and arrive-empty only on odd ones -> sync ops halved vs R11
// while register pressure stays at the R11 level. Same 48KB ring, 4 CTAs/SM.
// ---------------------------------------------------------------------------
__global__ __launch_bounds__(THREADS, 4) void multilevel_dense_kernel(
    const float* __restrict__ x,
    const float* __restrict__ w_mu,
    const float* __restrict__ w_sigma,
    const float* __restrict__ b_mu,
    const float* __restrict__ b_sigma,
    const float* __restrict__ eps_w,
    const float* __restrict__ eps_b,
    float* __restrict__ out)
{
    extern __shared__ __align__(128) char smem[];
    float4* ring = reinterpret_cast<float4*>(smem);               // 48 KB
    const uint32_t ring_sh = (uint32_t)__cvta_generic_to_shared(smem);
    const uint32_t mbar0   = ring_sh + RING_BYTES;                // 3 pairs
    // full[s] = mbar0 + s*16, empty[s] = mbar0 + s*16 + 8

    const int g    = blockIdx.y;
    const int u0   = blockIdx.x * UT;
    const int z    = blockIdx.z;
    const int tid  = threadIdx.x;
    const int warp = tid >> 5;
    const int lane = tid & 31;

    if (tid == 0) {
        #pragma unroll
        for (int s = 0; s < STAGES; s++) {
            mbar_init(mbar0 + s * 16,     1);       // full: producer expect_tx
            mbar_init(mbar0 + s * 16 + 8, CWARPS);  // empty: 1 arrive per consumer warp
        }
    }
    __syncthreads();   // mbarriers + smem visible; only CTA-wide barrier

    const int base = g_start[g] + z;
    const int end  = g_start[g + 1];
    const int nb   = (end > base) ? (end - base + SPLIT - 1) / SPLIT : 0;
    const int nst  = (nb + 1) >> 1;   // stages to fill (2 batches each)

    if (warp == CWARPS) {
        // ================= producer (lane 0 only) =================
        if (lane == 0) {
            int stage = 0, phase = 1;   // first empty-wait passes immediately
            for (int k2 = 0; k2 < nst; k2++) {
                mbar_wait(mbar0 + stage * 16 + 8, (uint32_t)phase);   // empty
                const int k0   = 2 * k2;
                const bool has1 = (k0 + 1) < nb;
                const uint32_t bytes = has1 ? STAGE_BYTES : HALF_BYTES;
                mbar_expect_tx(mbar0 + stage * 16, bytes);
                const uint32_t dst = ring_sh + (uint32_t)stage * STAGE_BYTES;
                const int b0 = g_items[base + k0 * SPLIT];
                bulk_copy_g2s(dst, eps_w + ((size_t)b0 * U + u0) * P,
                              HALF_BYTES, mbar0 + stage * 16);
                if (has1) {
                    const int b1 = g_items[base + (k0 + 1) * SPLIT];
                    bulk_copy_g2s(dst + HALF_BYTES,
                                  eps_w + ((size_t)b1 * U + u0) * P,
                                  HALF_BYTES, mbar0 + stage * 16);
                }
                if (++stage == STAGES) { stage = 0; phase ^= 1; }
            }
        }
        return;
    }

    // ================= consumers (warps 0-7, unit u = u0 + warp) =================
    const int u = u0 + warp;

    // persistent per-lane weights: features [lane*4..+4) and [128+lane*4..+4)
    float4 wA, wB, sA, sB;
    {
        const float4* wm4 = reinterpret_cast<const float4*>(w_mu    + ((size_t)g * U + u) * P);
        const float4* ws4 = reinterpret_cast<const float4*>(w_sigma + ((size_t)g * U + u) * P);
        wA = wm4[lane];
        wB = wm4[lane + 32];
        float4 vA = ws4[lane];
        float4 vB = ws4[lane + 32];
        sA.x = softplus_f(SOFTPLUS_C + vA.x);
        sA.y = softplus_f(SOFTPLUS_C + vA.y);
        sA.z = softplus_f(SOFTPLUS_C + vA.z);
        sA.w = softplus_f(SOFTPLUS_C + vA.w);
        sB.x = softplus_f(SOFTPLUS_C + vB.x);
        sB.y = softplus_f(SOFTPLUS_C + vB.y);
        sB.z = softplus_f(SOFTPLUS_C + vB.z);
        sB.w = softplus_f(SOFTPLUS_C + vB.w);
    }
    const float bmu = b_mu[g * U + u];
    const float spb = softplus_f(SOFTPLUS_C + b_sigma[g * U + u]);

    // this warp's 1KB slice base within a batch half (64 float4 per unit row)
    const int slice = warp * (P / 4);
    const int stage_f4 = STAGE_BYTES / 16;   // 1024 float4 per stage
    const int half_f4  = HALF_BYTES  / 16;   // 512  float4 per half

    int stage = 0, phase = 0;
    for (int k = 0; k < nb; k++) {
        const int half = k & 1;
        const int b = g_items[base + k * SPLIT];

        // prefetch x / eps_b BEFORE any wait (L1/L2 latency hidden)
        const float4* xb = reinterpret_cast<const float4*>(x + (size_t)b * P);
        float4 xa  = __ldg(&xb[lane]);
        float4 xbv = __ldg(&xb[lane + 32]);
        float  eb  = __ldg(&eps_b[(size_t)b * U + u]);

        if (!half)
            mbar_wait(mbar0 + stage * 16, (uint32_t)phase);   // full (acquire)

        const int bofs = stage * stage_f4 + half * half_f4 + slice;
        const float4 ea  = ring[bofs + lane];
        const float4 eb4 = ring[bofs + lane + 32];

        float acc = 0.0f;
        acc = fmaf(fmaf(sA.x, ea.x,  wA.x), xa.x,  acc);
        acc = fmaf(fmaf(sA.y, ea.y,  wA.y), xa.y,  acc);
        acc = fmaf(fmaf(sA.z, ea.z,  wA.z), xa.z,  acc);
        acc = fmaf(fmaf(sA.w, ea.w,  wA.w), xa.w,  acc);
        acc = fmaf(fmaf(sB.x, eb4.x, wB.x), xbv.x, acc);
        acc = fmaf(fmaf(sB.y, eb4.y, wB.y), xbv.y, acc);
        acc = fmaf(fmaf(sB.z, eb4.z, wB.z), xbv.z, acc);
        acc = fmaf(fmaf(sB.w, eb4.w, wB.w), xbv.w, acc);

        // release the stage once BOTH halves are consumed (or at the tail)
        const bool release = half || (k == nb - 1);
        if (release && lane == 0)
            mbar_arrive(mbar0 + stage * 16 + 8);   // empty

        acc = warp_sum(acc);   // producer keeps streaming during this tail

        if (lane == 0)
            out[(size_t)b * U + u] = acc + bmu + spb * eb;

        if (release) {
            if (++stage == STAGES) { stage = 0; phase ^= 1; }
        }
    }
}

// ---------------------------------------------------------------------------
// Launch
// Input order (metadata): x, gid, w_mu, w_sigma, b_mu, b_sigma, eps_w, eps_b
// ---------------------------------------------------------------------------
extern "C" void kernel_launch(void* const* d_in, const int* in_sizes, int n_in,
                              void* d_out, int out_size) {
    const float* x       = (const float*)d_in[0];
    const int*   gid     = (const int*)  d_in[1];
    const float* w_mu    = (const float*)d_in[2];
    const float* w_sigma = (const float*)d_in[3];
    const float* b_mu    = (const float*)d_in[4];
    const float* b_sigma = (const float*)d_in[5];
    const float* eps_w   = (const float*)d_in[6];
    const float* eps_b   = (const float*)d_in[7];
    float* out = (float*)d_out;

    // 1) bin batches by group
    bin_kernel<<<1, 256>>>(gid);

    // 2) warp-specialized main kernel (2 batches per ring stage)
    cudaFuncSetAttribute(multilevel_dense_kernel,
                         cudaFuncAttributeMaxDynamicSharedMemorySize, SMEM_TOTAL);
    dim3 grid(U / UT, G, SPLIT);   // (32, 64, 2) = 4096 CTAs
    multilevel_dense_kernel<<<grid, THREADS, SMEM_TOTAL>>>(
        x, w_mu, w_sigma, b_mu, b_sigma, eps_w, eps_b, out);
}

// round 13
// speedup vs baseline: 1.0943x; 1.0943x over previous
#include <cuda_runtime.h>
#include <cstdint>

// Problem constants (fixed by the reference)
static constexpr int B  = 2048;   // batch
static constexpr int U  = 256;    // units
static constexpr int P  = 256;    // features
static constexpr int G  = 64;     // groups
static constexpr int UT = 8;      // units per CTA (1 per warp)
static constexpr int SPLIT = 1;   // NO intra-group split: halves weight traffic,
                                  // halves CTA count (prologues, waves)

static constexpr int STAGES = 5;  // per-warp ring stages (1KB each) -> 40KB/CTA
static constexpr int DEPTH  = 3;  // cp.async groups in flight (R7 optimum)

#define SOFTPLUS_C 0.5413248546129181f

// Scratch (allocation-free rule: __device__ globals)
__device__ int g_items[B];        // batch indices sorted by group
__device__ int g_start[G + 1];    // group offsets into g_items

__device__ __forceinline__ float softplus_f(float v) {
    // numerically stable: max(v,0) + log1p(exp(-|v|)) (matches jax.nn.softplus f32)
    return fmaxf(v, 0.0f) + log1pf(expf(-fabsf(v)));
}

// warp sum: 5-step butterfly (sm_103 has NO redux.f32)
__device__ __forceinline__ float warp_sum(float v) {
    #pragma unroll
    for (int o = 16; o; o >>= 1) v += __shfl_xor_sync(0xffffffffu, v, o);
    return v;
}

// ---- cp.async helpers (.cg = L2-only, right for streaming eps) ----
__device__ __forceinline__ void cp_async16(uint32_t dst_smem, const void* src) {
    asm volatile("cp.async.cg.shared.global [%0], [%1], 16;\n"
                 :: "r"(dst_smem), "l"(src) : "memory");
}
__device__ __forceinline__ void cp_commit() {
    asm volatile("cp.async.commit_group;\n" ::: "memory");
}
template <int N>
__device__ __forceinline__ void cp_wait() {
    asm volatile("cp.async.wait_group %0;\n" :: "n"(N) : "memory");
}

// ---------------------------------------------------------------------------
// Kernel 1: counting-sort batches by group (single block, tiny)
// ---------------------------------------------------------------------------
__global__ void bin_kernel(const int* __restrict__ gid) {
    __shared__ int cnt[G];
    __shared__ int off[G];
    int tid = threadIdx.x;
    if (tid < G) cnt[tid] = 0;
    __syncthreads();
    for (int b = tid; b < B; b += blockDim.x)
        atomicAdd(&cnt[gid[b]], 1);
    __syncthreads();
    if (tid == 0) {
        int s = 0;
        for (int g = 0; g < G; g++) {
            g_start[g] = s;
            off[g] = s;
            s += cnt[g];
        }
        g_start[G] = s;
    }
    __syncthreads();
    for (int b = tid; b < B; b += blockDim.x) {
        int g = gid[b];
        int pos = atomicAdd(&off[g], 1);
        g_items[pos] = b;   // intra-group order nondeterministic; outputs are
                            // per-batch independent -> results deterministic
    }
}

// ---------------------------------------------------------------------------
// Kernel 2: main kernel — EXACTLY the 108.5us R7 machine, SPLIT=1.
// Zero barriers, register-resident weights, per-warp PRIVATE cp.async ring
// (5 stages x 1KB, depth 3 in flight). grid = (U/UT, G) = 2048 CTAs; each
// warp owns unit u = bx*8 + w of group g and streams ALL its batches (~32),
// so each weight slab is loaded exactly once chip-wide and prologue/wave
// overhead halves vs SPLIT=2.
// ---------------------------------------------------------------------------
__global__ __launch_bounds__(256) void multilevel_dense_kernel(
    const float* __restrict__ x,
    const float* __restrict__ w_mu,
    const float* __restrict__ w_sigma,
    const float* __restrict__ b_mu,
    const float* __restrict__ b_sigma,
    const float* __restrict__ eps_w,
    const float* __restrict__ eps_b,
    float* __restrict__ out)
{
    // per-warp private ring: [warp][stage][64 float4 slots] = 8*5*1KB = 40KB
    __shared__ __align__(16) float4 ring[UT][STAGES][P / 4];

    const int g    = blockIdx.y;
    const int warp = threadIdx.x >> 5;
    const int lane = threadIdx.x & 31;
    const int u    = blockIdx.x * UT + warp;

    // ---- persistent per-lane weights: features [lane*4..+4) and [128+lane*4..+4)
    float4 wA, wB, sA, sB;
    {
        const float4* wm4 = reinterpret_cast<const float4*>(w_mu    + ((size_t)g * U + u) * P);
        const float4* ws4 = reinterpret_cast<const float4*>(w_sigma + ((size_t)g * U + u) * P);
        wA = wm4[lane];
        wB = wm4[lane + 32];
        float4 vA = ws4[lane];
        float4 vB = ws4[lane + 32];
        sA.x = softplus_f(SOFTPLUS_C + vA.x);
        sA.y = softplus_f(SOFTPLUS_C + vA.y);
        sA.z = softplus_f(SOFTPLUS_C + vA.z);
        sA.w = softplus_f(SOFTPLUS_C + vA.w);
        sB.x = softplus_f(SOFTPLUS_C + vB.x);
        sB.y = softplus_f(SOFTPLUS_C + vB.y);
        sB.z = softplus_f(SOFTPLUS_C + vB.z);
        sB.w = softplus_f(SOFTPLUS_C + vB.w);
    }
    const float bmu = b_mu[g * U + u];
    const float spb = softplus_f(SOFTPLUS_C + b_sigma[g * U + u]);

    const int base = g_start[g];
    const int end  = g_start[g + 1];
    const int nb   = end - base;          // all batches of the group (SPLIT=1)

    const uint32_t ring_sh =
        (uint32_t)__cvta_generic_to_shared(&ring[warp][0][0]);

    // ---- prologue: fill DEPTH stages (one commit per stage, possibly empty)
    #pragma unroll
    for (int s = 0; s < DEPTH; s++) {
        if (s < nb) {
            const int b = g_items[base + s];
            const float4* e = reinterpret_cast<const float4*>(eps_w + ((size_t)b * U + u) * P);
            const uint32_t dst = ring_sh + (uint32_t)(s * (P / 4) * 16);
            cp_async16(dst + lane * 16,        e + lane);
            cp_async16(dst + (lane + 32) * 16, e + lane + 32);
        }
        cp_commit();
    }

    if (nb == 0) return;

    int stage  = 0;
    int b_cur  = g_items[base];

    for (int j = 0; j < nb; j++) {
        // prefetch next batch index (hides g_items L2 latency)
        const int b_nxt = (j + 1 < nb) ? g_items[base + j + 1] : 0;

        // issue cp.async for batch j+DEPTH into stage (stage+DEPTH)%STAGES
        {
            int ws = stage + DEPTH;
            if (ws >= STAGES) ws -= STAGES;
            if (j + DEPTH < nb) {
                const int bf = g_items[base + j + DEPTH];
                const float4* e = reinterpret_cast<const float4*>(eps_w + ((size_t)bf * U + u) * P);
                const uint32_t dst = ring_sh + (uint32_t)ws * (P / 4) * 16;
                cp_async16(dst + lane * 16,        e + lane);
                cp_async16(dst + (lane + 32) * 16, e + lane + 32);
            }
            cp_commit();
        }

        // x / eps_b loads for the CURRENT batch, issued before the wait
        const float4* xb = reinterpret_cast<const float4*>(x + (size_t)b_cur * P);
        float4 xa  = __ldg(&xb[lane]);
        float4 xbv = __ldg(&xb[lane + 32]);
        float  eb  = __ldg(&eps_b[(size_t)b_cur * U + u]);

        cp_wait<DEPTH>();   // oldest pending group (batch j's stage) complete

        const float4 ea  = ring[warp][stage][lane];
        const float4 eb4 = ring[warp][stage][lane + 32];

        float acc = 0.0f;
        acc = fmaf(fmaf(sA.x, ea.x,  wA.x), xa.x,  acc);
        acc = fmaf(fmaf(sA.y, ea.y,  wA.y), xa.y,  acc);
        acc = fmaf(fmaf(sA.z, ea.z,  wA.z), xa.z,  acc);
        acc = fmaf(fmaf(sA.w, ea.w,  wA.w), xa.w,  acc);
        acc = fmaf(fmaf(sB.x, eb4.x, wB.x), xbv.x, acc);
        acc = fmaf(fmaf(sB.y, eb4.y, wB.y), xbv.y, acc);
        acc = fmaf(fmaf(sB.z, eb4.z, wB.z), xbv.z, acc);
        acc = fmaf(fmaf(sB.w, eb4.w, wB.w), xbv.w, acc);

        acc = warp_sum(acc);   // 3 more stages in flight during this tail

        if (lane == 0)
            out[(size_t)b_cur * U + u] = acc + bmu + spb * eb;

        b_cur = b_nxt;
        if (++stage == STAGES) stage = 0;
    }
}

// ---------------------------------------------------------------------------
// Launch
// Input order (metadata): x, gid, w_mu, w_sigma, b_mu, b_sigma, eps_w, eps_b
// ---------------------------------------------------------------------------
extern "C" void kernel_launch(void* const* d_in, const int* in_sizes, int n_in,
                              void* d_out, int out_size) {
    const float* x       = (const float*)d_in[0];
    const int*   gid     = (const int*)  d_in[1];
    const float* w_mu    = (const float*)d_in[2];
    const float* w_sigma = (const float*)d_in[3];
    const float* b_mu    = (const float*)d_in[4];
    const float* b_sigma = (const float*)d_in[5];
    const float* eps_w   = (const float*)d_in[6];
    const float* eps_b   = (const float*)d_in[7];
    float* out = (float*)d_out;

    // 1) bin batches by group
    bin_kernel<<<1, 256>>>(gid);

    // 2) main kernel (R7 machine, SPLIT=1)
    dim3 grid(U / UT, G);   // (32, 64) = 2048 CTAs
    multilevel_dense_kernel<<<grid, 256>>>(x, w_mu, w_sigma, b_mu, b_sigma,
                                           eps_w, eps_b, out);
}